// round 2
// baseline (speedup 1.0000x reference)
#include <cuda_runtime.h>
#include <math.h>

#define NN   64      // batch
#define TDEC 100     // decoder text length
#define TS   99      // decode steps (T_DEC-1)
#define HD   512     // hidden dim (LSTM1)
#define KSZ  128     // key size (LSTM2 hidden)
#define VSZ  128     // value size
#define G1   2048    // 4*HD
#define G2   512     // 4*KSZ
#define TEN  512     // encoder length
#define VOC  32000

// ---------------- persistent device scratch (no allocs allowed) ----------------
__device__ float g_pre1[(size_t)TS * NN * G1];      // 51.9 MB: per-step gate base (emb part + biases)
__device__ float g_h1[NN * HD], g_c1[NN * HD];
__device__ float g_h2[NN * KSZ], g_c2[NN * KSZ];
__device__ float g_ctx[NN * VSZ];
__device__ float g_gates2[NN * G2];
__device__ float g_h2ctx[(size_t)TS * NN * (KSZ + VSZ)];  // 6.5 MB: staged [h2,ctx] rows

__device__ __forceinline__ float sigf(float x) { return 1.0f / (1.0f + expf(-x)); }

// ---------------- init: zero recurrent state ----------------
__global__ void init_kernel() {
    int i = blockIdx.x * blockDim.x + threadIdx.x;
    if (i < NN * HD)  { g_h1[i] = 0.f; g_c1[i] = 0.f; }
    if (i < NN * KSZ) { g_h2[i] = 0.f; g_c2[i] = 0.f; g_ctx[i] = 0.f; }
}

// ---------------- pre1: gates base = bih1+bhh1 + emb(text) @ Wih1[:, :512].T ----------------
// grid (16, 99): 64n x 128c tile, K=512.  8 rows x 4 cols per thread.
__global__ __launch_bounds__(256) void pre1_kernel(
    const int* __restrict__ text, const float* __restrict__ emb,
    const float* __restrict__ Wih1, const float* __restrict__ bih1,
    const float* __restrict__ bhh1)
{
    int t  = blockIdx.y;
    int cb = blockIdx.x * 128;
    int tx = threadIdx.x;
    int lane = tx & 31, warp = tx >> 5;

    __shared__ float sX[64][33];
    __shared__ float sW[32][128];

    float acc[8][4];
#pragma unroll
    for (int i = 0; i < 8; i++)
#pragma unroll
        for (int j = 0; j < 4; j++) acc[i][j] = 0.f;

    int ln  = tx >> 2;             // X-load row (n)
    int lkb = (tx & 3) * 8;        // X-load k base
    int tok = text[ln * TDEC + t];
    const float* erow = emb + (size_t)tok * HD;

    int wc  = tx & 127;            // W-load col
    int wkb = (tx >> 7) * 16;      // W-load k base
    const float* wrow = Wih1 + (size_t)(cb + wc) * 640;  // emb part: cols [0,512)

    for (int k0 = 0; k0 < HD; k0 += 32) {
#pragma unroll
        for (int i = 0; i < 8; i++) sX[ln][lkb + i] = erow[k0 + lkb + i];
#pragma unroll
        for (int i = 0; i < 16; i++) sW[wkb + i][wc] = wrow[k0 + wkb + i];
        __syncthreads();
#pragma unroll
        for (int kk = 0; kk < 32; kk++) {
            float wv[4];
#pragma unroll
            for (int j = 0; j < 4; j++) wv[j] = sW[kk][lane + 32 * j];
#pragma unroll
            for (int i = 0; i < 8; i++) {
                float xv = sX[warp * 8 + i][kk];
#pragma unroll
                for (int j = 0; j < 4; j++) acc[i][j] += xv * wv[j];
            }
        }
        __syncthreads();
    }
#pragma unroll
    for (int j = 0; j < 4; j++) {
        int c = cb + lane + 32 * j;
        float b = bih1[c] + bhh1[c];
#pragma unroll
        for (int i = 0; i < 8; i++) {
            int n = warp * 8 + i;
            g_pre1[((size_t)t * NN + n) * G1 + c] = acc[i][j] + b;
        }
    }
}

// ---------------- LSTM1 step GEMM: += [ctx(128),h1(512)] @ [Wih1[:,512:],Whh1].T ----------------
// grid (16 colgroups, 8 k-chunks of 80). Tile 64n x 128c (32 cols per gate region).
__global__ __launch_bounds__(256) void lstm1_gemm(
    const float* __restrict__ Wih1, const float* __restrict__ Whh1, int t)
{
    int cg = blockIdx.x;     // 0..15
    int ky = blockIdx.y;     // 0..7
    int tx = threadIdx.x;
    int lane = tx & 31, warp = tx >> 5;

    __shared__ float sX[64][17];
    __shared__ float sW[16][128];

    float acc[8][4];
#pragma unroll
    for (int i = 0; i < 8; i++)
#pragma unroll
        for (int j = 0; j < 4; j++) acc[i][j] = 0.f;

    int ln  = tx >> 2;          // X row
    int lkb = (tx & 3) * 4;     // X k base (4 each)
    int wc  = tx & 127;
    int wkb = (tx >> 7) * 8;    // W k base (8 each)
    int grW = (wc >> 5) * 512 + cg * 32 + (wc & 31);
    const float* wih = Wih1 + (size_t)grW * 640 + 512;  // ctx part of Wih1
    const float* whh = Whh1 + (size_t)grW * 512;

    for (int k0 = 0; k0 < 80; k0 += 16) {
        int kbase = ky * 80 + k0;
#pragma unroll
        for (int i = 0; i < 4; i++) {
            int kg = kbase + lkb + i;
            sX[ln][lkb + i] = (kg < 128) ? g_ctx[ln * VSZ + kg] : g_h1[ln * HD + kg - 128];
        }
#pragma unroll
        for (int i = 0; i < 8; i++) {
            int kg = kbase + wkb + i;
            sW[wkb + i][wc] = (kg < 128) ? wih[kg] : whh[kg - 128];
        }
        __syncthreads();
#pragma unroll
        for (int kk = 0; kk < 16; kk++) {
            float wv[4];
#pragma unroll
            for (int j = 0; j < 4; j++) wv[j] = sW[kk][lane + 32 * j];
#pragma unroll
            for (int i = 0; i < 8; i++) {
                float xv = sX[warp * 8 + i][kk];
#pragma unroll
                for (int j = 0; j < 4; j++) acc[i][j] += xv * wv[j];
            }
        }
        __syncthreads();
    }
#pragma unroll
    for (int j = 0; j < 4; j++) {
        int gcol = j * 512 + cg * 32 + lane;
#pragma unroll
        for (int i = 0; i < 8; i++) {
            int n = warp * 8 + i;
            atomicAdd(&g_pre1[((size_t)t * NN + n) * G1 + gcol], acc[i][j]);
        }
    }
}

// ---------------- LSTM1 cell update + LSTM2 gate-buffer bias init ----------------
__global__ void cell1_kernel(const float* __restrict__ bih2,
                             const float* __restrict__ bhh2, int t)
{
    int idx = blockIdx.x * blockDim.x + threadIdx.x;   // 64*512
    int n = idx >> 9, k = idx & 511;
    const float* gp = g_pre1 + ((size_t)t * NN + n) * G1;
    float gi = gp[k], gf = gp[512 + k], gg = gp[1024 + k], go = gp[1536 + k];
    float c = sigf(gf) * g_c1[idx] + sigf(gi) * tanhf(gg);
    g_c1[idx] = c;
    g_h1[idx] = sigf(go) * tanhf(c);
    g_gates2[idx] = bih2[k] + bhh2[k];
}

// ---------------- LSTM2 step GEMM: += [h1(512),h2(128)] @ [Wih2,Whh2].T ----------------
// grid (8 colgroups, 8 k-chunks of 80). Tile 64n x 64c (16 cols per gate region).
__global__ __launch_bounds__(256) void lstm2_gemm(
    const float* __restrict__ Wih2, const float* __restrict__ Whh2)
{
    int cg = blockIdx.x;   // 0..7
    int ky = blockIdx.y;   // 0..7
    int tx = threadIdx.x;
    int lane = tx & 31, warp = tx >> 5;

    __shared__ float sX[64][17];
    __shared__ float sW[16][64];

    float acc[8][2];
#pragma unroll
    for (int i = 0; i < 8; i++) { acc[i][0] = 0.f; acc[i][1] = 0.f; }

    int ln  = tx >> 2;
    int lkb = (tx & 3) * 4;
    int wc  = tx & 63;
    int wkb = (tx >> 6) * 4;
    int grW = (wc >> 4) * 128 + cg * 16 + (wc & 15);
    const float* wih = Wih2 + (size_t)grW * 512;
    const float* whh = Whh2 + (size_t)grW * 128;

    for (int k0 = 0; k0 < 80; k0 += 16) {
        int kbase = ky * 80 + k0;
#pragma unroll
        for (int i = 0; i < 4; i++) {
            int kg = kbase + lkb + i;
            sX[ln][lkb + i] = (kg < 512) ? g_h1[ln * HD + kg] : g_h2[ln * KSZ + kg - 512];
        }
#pragma unroll
        for (int i = 0; i < 4; i++) {
            int kg = kbase + wkb + i;
            sW[wkb + i][wc] = (kg < 512) ? wih[kg] : whh[kg - 512];
        }
        __syncthreads();
#pragma unroll
        for (int kk = 0; kk < 16; kk++) {
            float wv[2];
            wv[0] = sW[kk][lane];
            wv[1] = sW[kk][lane + 32];
#pragma unroll
            for (int i = 0; i < 8; i++) {
                float xv = sX[warp * 8 + i][kk];
                acc[i][0] += xv * wv[0];
                acc[i][1] += xv * wv[1];
            }
        }
        __syncthreads();
    }
#pragma unroll
    for (int j = 0; j < 2; j++) {
        int cc = lane + 32 * j;
        int gcol = (cc >> 4) * 128 + cg * 16 + (cc & 15);
#pragma unroll
        for (int i = 0; i < 8; i++) {
            int n = warp * 8 + i;
            atomicAdd(&g_gates2[n * G2 + gcol], acc[i][j]);
        }
    }
}

// ---------------- LSTM2 cell + masked-softmax attention + context; writes attn maps ----------------
// grid 64 (one block per batch row), 256 threads
__global__ __launch_bounds__(256) void attn_kernel(
    const float* __restrict__ enc_key, const float* __restrict__ values,
    const int* __restrict__ lens, float* __restrict__ out_attn, int t)
{
    int n = blockIdx.x;
    int tx = threadIdx.x;
    __shared__ __align__(16) float sh2[128];
    __shared__ float se[512];
    __shared__ float sred[256];

    // LSTM2 cell update (gates complete in g_gates2)
    if (tx < 128) {
        const float* g = g_gates2 + n * G2;
        float gi = g[tx], gf = g[128 + tx], gg = g[256 + tx], go = g[384 + tx];
        float c = sigf(gf) * g_c2[n * KSZ + tx] + sigf(gi) * tanhf(gg);
        g_c2[n * KSZ + tx] = c;
        float h = sigf(go) * tanhf(c);
        g_h2[n * KSZ + tx] = h;
        sh2[tx] = h;
        g_h2ctx[((size_t)t * NN + n) * 256 + tx] = h;
    }
    __syncthreads();

    // energies: e[te] = enc_key[n,te,:] . h2
#pragma unroll
    for (int te = tx; te < TEN; te += 256) {
        const float4* er = (const float4*)(enc_key + ((size_t)n * TEN + te) * KSZ);
        const float4* h4 = (const float4*)sh2;
        float e = 0.f;
#pragma unroll
        for (int q = 0; q < 32; q++) {
            float4 a = er[q], b = h4[q];
            e += a.x * b.x + a.y * b.y + a.z * b.z + a.w * b.w;
        }
        se[te] = e;
    }
    __syncthreads();

    // max reduce
    float lm = fmaxf(se[tx], se[tx + 256]);
    sred[tx] = lm;
    __syncthreads();
    for (int s = 128; s > 0; s >>= 1) {
        if (tx < s) sred[tx] = fmaxf(sred[tx], sred[tx + s]);
        __syncthreads();
    }
    float M = sred[0];
    int len = lens[n];

    float ls = 0.f;
#pragma unroll
    for (int te = tx; te < TEN; te += 256) {
        float p = (te < len) ? expf(se[te] - M) : 0.f;
        se[te] = p;
        ls += p;
    }
    __syncthreads();
    sred[tx] = ls;
    __syncthreads();
    for (int s = 128; s > 0; s >>= 1) {
        if (tx < s) sred[tx] += sred[tx + s];
        __syncthreads();
    }
    float inv = 1.f / sred[0];
    __syncthreads();

#pragma unroll
    for (int te = tx; te < TEN; te += 256) {
        float a = se[te] * inv;
        se[te] = a;
        out_attn[((size_t)n * TS + t) * TEN + te] = a;
    }
    __syncthreads();

    // context[v] = sum_te attn[te] * values[n,te,v]
    int v = tx & 127, half = tx >> 7;
    float accv = 0.f;
    const float* vb = values + ((size_t)n * TEN + half * 256) * VSZ + v;
#pragma unroll 8
    for (int it = 0; it < 256; it++) accv += se[half * 256 + it] * vb[it * VSZ];
    sred[tx] = accv;
    __syncthreads();
    if (tx < 128) {
        float cv = sred[tx] + sred[tx + 128];
        g_ctx[n * VSZ + tx] = cv;
        g_h2ctx[((size_t)t * NN + n) * 256 + 128 + tx] = cv;
    }
}

// ---------------- output projection: pred = [h2,ctx] @ Wout.T + bout ----------------
// grid (500, 99): 64row x 64col tile, K=256. 4x4 outputs per thread.
__global__ __launch_bounds__(256) void out_gemm(
    const float* __restrict__ Wout, const float* __restrict__ bout,
    float* __restrict__ pred)
{
    int cb = blockIdx.x * 64;
    int t  = blockIdx.y;
    int tx = threadIdx.x;
    int lane = tx & 31;
    int rg = tx >> 4;          // rows rg*4 .. rg*4+3
    int cl = lane & 15;        // cols cl + 16j

    __shared__ float sX[64][33];
    __shared__ float sW[32][65];

    float acc[4][4];
#pragma unroll
    for (int i = 0; i < 4; i++)
#pragma unroll
        for (int j = 0; j < 4; j++) acc[i][j] = 0.f;

    int ln  = tx >> 2;
    int lkb = (tx & 3) * 8;
    const float* xrow = g_h2ctx + ((size_t)t * NN + ln) * 256;
    int wc  = tx & 63;
    int wkb = (tx >> 6) * 8;
    const float* wrow = Wout + (size_t)(cb + wc) * 256;

    for (int k0 = 0; k0 < 256; k0 += 32) {
#pragma unroll
        for (int i = 0; i < 8; i++) sX[ln][lkb + i] = xrow[k0 + lkb + i];
#pragma unroll
        for (int i = 0; i < 8; i++) sW[wkb + i][wc] = wrow[k0 + wkb + i];
        __syncthreads();
#pragma unroll
        for (int kk = 0; kk < 32; kk++) {
            float wv[4];
#pragma unroll
            for (int j = 0; j < 4; j++) wv[j] = sW[kk][cl + 16 * j];
#pragma unroll
            for (int i = 0; i < 4; i++) {
                float xv = sX[rg * 4 + i][kk];
#pragma unroll
                for (int j = 0; j < 4; j++) acc[i][j] += xv * wv[j];
            }
        }
        __syncthreads();
    }
#pragma unroll
    for (int j = 0; j < 4; j++) {
        int c = cb + cl + 16 * j;
        float b = bout[c];
#pragma unroll
        for (int i = 0; i < 4; i++) {
            int n = rg * 4 + i;
            pred[(size_t)n * ((size_t)TS * VOC) + (size_t)t * VOC + c] = acc[i][j] + b;
        }
    }
}

// ---------------- launch ----------------
extern "C" void kernel_launch(void* const* d_in, const int* in_sizes, int n_in,
                              void* d_out, int out_size)
{
    const float* enc_key = (const float*)d_in[0];
    const float* values  = (const float*)d_in[1];
    const int*   lens    = (const int*)d_in[2];
    const int*   text    = (const int*)d_in[3];
    const float* emb     = (const float*)d_in[4];
    const float* Wih1    = (const float*)d_in[5];
    const float* Whh1    = (const float*)d_in[6];
    const float* bih1    = (const float*)d_in[7];
    const float* bhh1    = (const float*)d_in[8];
    const float* Wih2    = (const float*)d_in[9];
    const float* Whh2    = (const float*)d_in[10];
    const float* bih2    = (const float*)d_in[11];
    const float* bhh2    = (const float*)d_in[12];
    const float* Wout    = (const float*)d_in[13];
    const float* bout    = (const float*)d_in[14];

    float* pred = (float*)d_out;
    float* attn = (float*)d_out + (size_t)NN * TS * VOC;

    init_kernel<<<128, 256>>>();
    pre1_kernel<<<dim3(16, TS), 256>>>(text, emb, Wih1, bih1, bhh1);
    for (int t = 0; t < TS; t++) {
        lstm1_gemm<<<dim3(16, 8), 256>>>(Wih1, Whh1, t);
        cell1_kernel<<<128, 256>>>(bih2, bhh2, t);
        lstm2_gemm<<<dim3(8, 8), 256>>>(Wih2, Whh2);
        attn_kernel<<<64, 256>>>(enc_key, values, lens, attn, t);
    }
    out_gemm<<<dim3(500, TS), 256>>>(Wout, bout, pred);
}